// round 12
// baseline (speedup 1.0000x reference)
#include <cuda_runtime.h>
#include <math.h>

#define SEQ   2048
#define DM    1024
#define NH    16
#define HD    64
#define DFF   4096
#define NL    4
#define WIN   128

// ---------------- scratch (device globals; no runtime allocation) ----------
__device__ float g_x  [SEQ * DM];        // residual stream
__device__ float g_qkv[SEQ * 3 * DM];    // fused qkv
__device__ float g_att[SEQ * DM];        // attention output
__device__ float g_h  [SEQ * DFF];       // FF hidden
__device__ float g_y  [SEQ * DM];        // proj / FF2 output

// ---------------- positional encoding add (fp64 trig: fast-math immune) ----
__global__ void add_pe_kernel(const float* __restrict__ X, float* __restrict__ x)
{
    int i = blockIdx.x * 256 + threadIdx.x;       // over SEQ*DM
    int s = i >> 10;
    int d = i & 1023;
    double dv  = exp((double)(d & ~1) * (-9.210340371976184 / 1024.0));
    double ang = (double)s * dv;
    float pe = (d & 1) ? (float)cos(ang) : (float)sin(ang);
    x[i] = X[i] + pe;
}

// ---------------- GEMM NT: C[M,N] = A[M,K] * B[N,K]^T + bias, opt ReLU -----
// 128x128 tile, BK=16, 256 threads, 8x8 per-thread register tile.
template<int RELU>
__global__ __launch_bounds__(256) void gemm_nt(
    const float* __restrict__ A, const float* __restrict__ B,
    const float* __restrict__ bias, float* __restrict__ C,
    int M, int N, int K)
{
    __shared__ float As[16][132];
    __shared__ float Bs[16][132];

    const int tid = threadIdx.x;
    const int m0  = blockIdx.y * 128;
    const int n0  = blockIdx.x * 128;
    const int tr  = tid >> 4;       // 0..15
    const int tc  = tid & 15;       // 0..15

    float acc[8][8];
    #pragma unroll
    for (int i = 0; i < 8; i++)
        #pragma unroll
        for (int j = 0; j < 8; j++) acc[i][j] = 0.f;

    for (int k0 = 0; k0 < K; k0 += 16) {
        #pragma unroll
        for (int i = 0; i < 2; i++) {
            int idx = tid + 256 * i;          // 0..511
            int r   = idx >> 2;               // 0..127
            int kc  = (idx & 3) << 2;         // 0,4,8,12
            float4 va = *(const float4*)(A + (size_t)(m0 + r) * K + k0 + kc);
            As[kc + 0][r] = va.x; As[kc + 1][r] = va.y;
            As[kc + 2][r] = va.z; As[kc + 3][r] = va.w;
            float4 vb = *(const float4*)(B + (size_t)(n0 + r) * K + k0 + kc);
            Bs[kc + 0][r] = vb.x; Bs[kc + 1][r] = vb.y;
            Bs[kc + 2][r] = vb.z; Bs[kc + 3][r] = vb.w;
        }
        __syncthreads();
        #pragma unroll
        for (int kk = 0; kk < 16; kk++) {
            float a[8], b[8];
            *(float4*)(a)     = *(const float4*)&As[kk][tr * 8];
            *(float4*)(a + 4) = *(const float4*)&As[kk][tr * 8 + 4];
            *(float4*)(b)     = *(const float4*)&Bs[kk][tc * 8];
            *(float4*)(b + 4) = *(const float4*)&Bs[kk][tc * 8 + 4];
            #pragma unroll
            for (int i = 0; i < 8; i++)
                #pragma unroll
                for (int j = 0; j < 8; j++)
                    acc[i][j] += a[i] * b[j];
        }
        __syncthreads();
    }

    #pragma unroll
    for (int i = 0; i < 8; i++) {
        int row = m0 + tr * 8 + i;
        #pragma unroll
        for (int j = 0; j < 8; j += 4) {
            int col = n0 + tc * 8 + j;
            float4 v;
            v.x = acc[i][j + 0] + bias[col + 0];
            v.y = acc[i][j + 1] + bias[col + 1];
            v.z = acc[i][j + 2] + bias[col + 2];
            v.w = acc[i][j + 3] + bias[col + 3];
            if (RELU) {
                v.x = fmaxf(v.x, 0.f); v.y = fmaxf(v.y, 0.f);
                v.z = fmaxf(v.z, 0.f); v.w = fmaxf(v.w, 0.f);
            }
            *(float4*)(C + (size_t)row * N + col) = v;
        }
    }
}

// ---------------- banded flash attention --------------------------------
// grid: (SEQ/128, NH), 128 threads. Each thread owns one query row (q, o in
// registers), streams 32-row K/V tiles through shared memory, online softmax.
__global__ __launch_bounds__(128) void attention_kernel(
    const float* __restrict__ qkv, float* __restrict__ out)
{
    const int h   = blockIdx.y;
    const int r0  = blockIdx.x * 128;
    const int tid = threadIdx.x;
    const int row = r0 + tid;

    __shared__ float ks[32][64];
    __shared__ float vs[32][64];

    float q[64];
    {
        const float4* qp = (const float4*)(qkv + (size_t)row * (3 * DM) + h * HD);
        #pragma unroll
        for (int i = 0; i < 16; i++) {
            float4 v = qp[i];
            q[4*i+0] = v.x * 0.125f; q[4*i+1] = v.y * 0.125f;
            q[4*i+2] = v.z * 0.125f; q[4*i+3] = v.w * 0.125f;
        }
    }
    float o[64];
    #pragma unroll
    for (int d = 0; d < 64; d++) o[d] = 0.f;
    float m = -INFINITY, l = 0.f;

    int cmin = r0 - (WIN - 1); if (cmin < 0) cmin = 0;
    int cmax = r0 + 127 + (WIN - 1); if (cmax > SEQ - 1) cmax = SEQ - 1;

    for (int c0 = cmin & ~31; c0 <= cmax; c0 += 32) {
        __syncthreads();
        #pragma unroll
        for (int i = 0; i < 4; i++) {
            int idx = tid + 128 * i;          // 0..511
            int r   = idx >> 4;               // 0..31
            int d4  = (idx & 15) << 2;        // 0..60
            *(float4*)&ks[r][d4] =
                *(const float4*)(qkv + (size_t)(c0 + r) * (3 * DM) + DM + h * HD + d4);
            *(float4*)&vs[r][d4] =
                *(const float4*)(qkv + (size_t)(c0 + r) * (3 * DM) + 2 * DM + h * HD + d4);
        }
        __syncthreads();

        float sc[32];
        #pragma unroll
        for (int c = 0; c < 32; c++) {
            float a = 0.f;
            #pragma unroll
            for (int d = 0; d < 64; d++) a += q[d] * ks[c][d];
            sc[c] = a;
        }
        float mnew = m;
        #pragma unroll
        for (int c = 0; c < 32; c++) {
            int col  = c0 + c;
            int diff = row - col; diff = (diff < 0) ? -diff : diff;
            if (diff >= WIN) sc[c] = -INFINITY;
            else if (sc[c] > mnew) mnew = sc[c];
        }
        if (mnew != -INFINITY) {
            float corr = expf(m - mnew);      // m=-inf -> 0
            l *= corr;
            #pragma unroll
            for (int d = 0; d < 64; d++) o[d] *= corr;
            #pragma unroll
            for (int c = 0; c < 32; c++) {
                float p = (sc[c] == -INFINITY) ? 0.f : expf(sc[c] - mnew);
                l += p;
                #pragma unroll
                for (int d = 0; d < 64; d++) o[d] += p * vs[c][d];
            }
            m = mnew;
        }
    }

    float invl = 1.f / l;
    float* op = out + (size_t)row * DM + h * HD;
    #pragma unroll
    for (int i = 0; i < 16; i++) {
        float4 v = make_float4(o[4*i+0]*invl, o[4*i+1]*invl, o[4*i+2]*invl, o[4*i+3]*invl);
        *(float4*)(op + 4 * i) = v;
    }
}

// ---------------- fused residual + LayerNorm (in-place on x) -------------
__global__ __launch_bounds__(256) void ln_residual_kernel(
    float* __restrict__ x, const float* __restrict__ y,
    const float* __restrict__ g, const float* __restrict__ b)
{
    int s = blockIdx.x, t = threadIdx.x;
    float* xr = x + (size_t)s * DM;
    const float* yr = y + (size_t)s * DM;

    float v[4], sum = 0.f, sq = 0.f;
    #pragma unroll
    for (int i = 0; i < 4; i++) {
        int d = i * 256 + t;
        v[i] = xr[d] + yr[d];
        sum += v[i];
        sq  += v[i] * v[i];
    }
    #pragma unroll
    for (int off = 16; off; off >>= 1) {
        sum += __shfl_xor_sync(0xffffffffu, sum, off);
        sq  += __shfl_xor_sync(0xffffffffu, sq,  off);
    }
    __shared__ float s_sum[8], s_sq[8];
    int w = t >> 5;
    if ((t & 31) == 0) { s_sum[w] = sum; s_sq[w] = sq; }
    __syncthreads();
    float ts = 0.f, tq = 0.f;
    #pragma unroll
    for (int i = 0; i < 8; i++) { ts += s_sum[i]; tq += s_sq[i]; }

    float mean = ts * (1.f / DM);
    float var  = tq * (1.f / DM) - mean * mean;
    var = fmaxf(var, 0.f);
    float inv = rsqrtf(var + 1e-5f);
    #pragma unroll
    for (int i = 0; i < 4; i++) {
        int d = i * 256 + t;
        xr[d] = (v[i] - mean) * inv * g[d] + b[d];
    }
}

// ---------------- decoder: logits (D->3) + log_softmax -------------------
__global__ __launch_bounds__(128) void decode_kernel(
    const float* __restrict__ x, const float* __restrict__ W,
    const float* __restrict__ bd, float* __restrict__ out)
{
    int s = blockIdx.x, t = threadIdx.x;
    const float* xr = x + (size_t)s * DM;
    float p0 = 0.f, p1 = 0.f, p2 = 0.f;
    for (int d = t; d < DM; d += 128) {
        float xv = xr[d];
        p0 += xv * W[d];
        p1 += xv * W[DM + d];
        p2 += xv * W[2 * DM + d];
    }
    #pragma unroll
    for (int off = 16; off; off >>= 1) {
        p0 += __shfl_xor_sync(0xffffffffu, p0, off);
        p1 += __shfl_xor_sync(0xffffffffu, p1, off);
        p2 += __shfl_xor_sync(0xffffffffu, p2, off);
    }
    __shared__ float r0[4], r1[4], r2[4];
    int w = t >> 5;
    if ((t & 31) == 0) { r0[w] = p0; r1[w] = p1; r2[w] = p2; }
    __syncthreads();
    if (t == 0) {
        float l0 = r0[0]+r0[1]+r0[2]+r0[3] + bd[0];
        float l1 = r1[0]+r1[1]+r1[2]+r1[3] + bd[1];
        float l2 = r2[0]+r2[1]+r2[2]+r2[3] + bd[2];
        float mx  = fmaxf(l0, fmaxf(l1, l2));
        float lse = mx + logf(expf(l0-mx) + expf(l1-mx) + expf(l2-mx));
        out[s*3+0] = l0 - lse;
        out[s*3+1] = l1 - lse;
        out[s*3+2] = l2 - lse;
    }
}

// ---------------- launch ---------------------------------------------------
extern "C" void kernel_launch(void* const* d_in, const int* in_sizes, int n_in,
                              void* d_out, int out_size)
{
    const float* X     = (const float*)d_in[0];
    const float* Wqkv  = (const float*)d_in[1];
    const float* bqkv  = (const float*)d_in[2];
    const float* Wo    = (const float*)d_in[3];
    const float* bo    = (const float*)d_in[4];
    const float* ln1g  = (const float*)d_in[5];
    const float* ln1b  = (const float*)d_in[6];
    const float* W1    = (const float*)d_in[7];
    const float* b1    = (const float*)d_in[8];
    const float* W2    = (const float*)d_in[9];
    const float* b2    = (const float*)d_in[10];
    const float* ln2g  = (const float*)d_in[11];
    const float* ln2b  = (const float*)d_in[12];
    const float* Wdec  = (const float*)d_in[13];
    const float* bdec  = (const float*)d_in[14];

    float *x, *qkv, *att, *hbuf, *ybuf;
    cudaGetSymbolAddress((void**)&x,    g_x);
    cudaGetSymbolAddress((void**)&qkv,  g_qkv);
    cudaGetSymbolAddress((void**)&att,  g_att);
    cudaGetSymbolAddress((void**)&hbuf, g_h);
    cudaGetSymbolAddress((void**)&ybuf, g_y);

    add_pe_kernel<<<(SEQ * DM) / 256, 256>>>(X, x);

    for (int l = 0; l < NL; l++) {
        // QKV projection: [2048,1024] x [3072,1024]^T
        gemm_nt<0><<<dim3(3 * DM / 128, SEQ / 128), 256>>>(
            x, Wqkv + (size_t)l * 3 * DM * DM, bqkv + (size_t)l * 3 * DM,
            qkv, SEQ, 3 * DM, DM);

        // banded attention
        attention_kernel<<<dim3(SEQ / 128, NH), 128>>>(qkv, att);

        // output projection
        gemm_nt<0><<<dim3(DM / 128, SEQ / 128), 256>>>(
            att, Wo + (size_t)l * DM * DM, bo + (size_t)l * DM,
            ybuf, SEQ, DM, DM);

        // x = LN1(x + attn_proj)
        ln_residual_kernel<<<SEQ, 256>>>(x, ybuf, ln1g + (size_t)l * DM, ln1b + (size_t)l * DM);

        // FF1 + ReLU: [2048,1024] x [4096,1024]^T
        gemm_nt<1><<<dim3(DFF / 128, SEQ / 128), 256>>>(
            x, W1 + (size_t)l * DFF * DM, b1 + (size_t)l * DFF,
            hbuf, SEQ, DFF, DM);

        // FF2: [2048,4096] x [1024,4096]^T
        gemm_nt<0><<<dim3(DM / 128, SEQ / 128), 256>>>(
            hbuf, W2 + (size_t)l * DM * DFF, b2 + (size_t)l * DM,
            ybuf, SEQ, DM, DFF);

        // x = LN2(x + ff)
        ln_residual_kernel<<<SEQ, 256>>>(x, ybuf, ln2g + (size_t)l * DM, ln2b + (size_t)l * DM);
    }

    decode_kernel<<<SEQ, 128>>>(x, Wdec, bdec, (float*)d_out);
}

// round 13
// speedup vs baseline: 1.0001x; 1.0001x over previous
#include <cuda_runtime.h>
#include <math.h>

#define SEQ   2048
#define DM    1024
#define NH    16
#define HD    64
#define DFF   4096
#define NL    4
#define WIN   128

// ---------------- scratch (device globals; no runtime allocation) ----------
__device__ float g_x  [SEQ * DM];        // residual stream
__device__ float g_qkv[SEQ * 3 * DM];    // fused qkv
__device__ float g_att[SEQ * DM];        // attention output
__device__ float g_h  [SEQ * DFF];       // FF hidden
__device__ float g_y  [SEQ * DM];        // proj / FF2 output

// ---------------- positional encoding add (fp64 trig: fast-math immune) ----
__global__ void add_pe_kernel(const float* __restrict__ X, float* __restrict__ x)
{
    int i = blockIdx.x * 256 + threadIdx.x;       // over SEQ*DM
    int s = i >> 10;
    int d = i & 1023;
    double dv  = exp((double)(d & ~1) * (-9.210340371976184 / 1024.0));
    double ang = (double)s * dv;
    float pe = (d & 1) ? (float)cos(ang) : (float)sin(ang);
    x[i] = X[i] + pe;
}

// ---------------- GEMM NT: C[M,N] = A[M,K] * B[N,K]^T + bias, opt ReLU -----
// 128x128 tile, BK=16, 256 threads, 8x8 per-thread register tile.
template<int RELU>
__global__ __launch_bounds__(256) void gemm_nt(
    const float* __restrict__ A, const float* __restrict__ B,
    const float* __restrict__ bias, float* __restrict__ C,
    int M, int N, int K)
{
    __shared__ float As[16][132];
    __shared__ float Bs[16][132];

    const int tid = threadIdx.x;
    const int m0  = blockIdx.y * 128;
    const int n0  = blockIdx.x * 128;
    const int tr  = tid >> 4;       // 0..15
    const int tc  = tid & 15;       // 0..15

    float acc[8][8];
    #pragma unroll
    for (int i = 0; i < 8; i++)
        #pragma unroll
        for (int j = 0; j < 8; j++) acc[i][j] = 0.f;

    for (int k0 = 0; k0 < K; k0 += 16) {
        #pragma unroll
        for (int i = 0; i < 2; i++) {
            int idx = tid + 256 * i;          // 0..511
            int r   = idx >> 2;               // 0..127
            int kc  = (idx & 3) << 2;         // 0,4,8,12
            float4 va = *(const float4*)(A + (size_t)(m0 + r) * K + k0 + kc);
            As[kc + 0][r] = va.x; As[kc + 1][r] = va.y;
            As[kc + 2][r] = va.z; As[kc + 3][r] = va.w;
            float4 vb = *(const float4*)(B + (size_t)(n0 + r) * K + k0 + kc);
            Bs[kc + 0][r] = vb.x; Bs[kc + 1][r] = vb.y;
            Bs[kc + 2][r] = vb.z; Bs[kc + 3][r] = vb.w;
        }
        __syncthreads();
        #pragma unroll
        for (int kk = 0; kk < 16; kk++) {
            float a[8], b[8];
            *(float4*)(a)     = *(const float4*)&As[kk][tr * 8];
            *(float4*)(a + 4) = *(const float4*)&As[kk][tr * 8 + 4];
            *(float4*)(b)     = *(const float4*)&Bs[kk][tc * 8];
            *(float4*)(b + 4) = *(const float4*)&Bs[kk][tc * 8 + 4];
            #pragma unroll
            for (int i = 0; i < 8; i++)
                #pragma unroll
                for (int j = 0; j < 8; j++)
                    acc[i][j] += a[i] * b[j];
        }
        __syncthreads();
    }

    #pragma unroll
    for (int i = 0; i < 8; i++) {
        int row = m0 + tr * 8 + i;
        #pragma unroll
        for (int j = 0; j < 8; j += 4) {
            int col = n0 + tc * 8 + j;
            float4 v;
            v.x = acc[i][j + 0] + bias[col + 0];
            v.y = acc[i][j + 1] + bias[col + 1];
            v.z = acc[i][j + 2] + bias[col + 2];
            v.w = acc[i][j + 3] + bias[col + 3];
            if (RELU) {
                v.x = fmaxf(v.x, 0.f); v.y = fmaxf(v.y, 0.f);
                v.z = fmaxf(v.z, 0.f); v.w = fmaxf(v.w, 0.f);
            }
            *(float4*)(C + (size_t)row * N + col) = v;
        }
    }
}

// ---------------- banded flash attention --------------------------------
// grid: (SEQ/128, NH), 128 threads. Each thread owns one query row (q, o in
// registers), streams 32-row K/V tiles through shared memory, online softmax.
__global__ __launch_bounds__(128) void attention_kernel(
    const float* __restrict__ qkv, float* __restrict__ out)
{
    const int h   = blockIdx.y;
    const int r0  = blockIdx.x * 128;
    const int tid = threadIdx.x;
    const int row = r0 + tid;

    __shared__ float ks[32][64];
    __shared__ float vs[32][64];

    float q[64];
    {
        const float4* qp = (const float4*)(qkv + (size_t)row * (3 * DM) + h * HD);
        #pragma unroll
        for (int i = 0; i < 16; i++) {
            float4 v = qp[i];
            q[4*i+0] = v.x * 0.125f; q[4*i+1] = v.y * 0.125f;
            q[4*i+2] = v.z * 0.125f; q[4*i+3] = v.w * 0.125f;
        }
    }
    float o[64];
    #pragma unroll
    for (int d = 0; d < 64; d++) o[d] = 0.f;
    float m = -INFINITY, l = 0.f;

    int cmin = r0 - (WIN - 1); if (cmin < 0) cmin = 0;
    int cmax = r0 + 127 + (WIN - 1); if (cmax > SEQ - 1) cmax = SEQ - 1;

    for (int c0 = cmin & ~31; c0 <= cmax; c0 += 32) {
        __syncthreads();
        #pragma unroll
        for (int i = 0; i < 4; i++) {
            int idx = tid + 128 * i;          // 0..511
            int r   = idx >> 4;               // 0..31
            int d4  = (idx & 15) << 2;        // 0..60
            *(float4*)&ks[r][d4] =
                *(const float4*)(qkv + (size_t)(c0 + r) * (3 * DM) + DM + h * HD + d4);
            *(float4*)&vs[r][d4] =
                *(const float4*)(qkv + (size_t)(c0 + r) * (3 * DM) + 2 * DM + h * HD + d4);
        }
        __syncthreads();

        float sc[32];
        #pragma unroll
        for (int c = 0; c < 32; c++) {
            float a = 0.f;
            #pragma unroll
            for (int d = 0; d < 64; d++) a += q[d] * ks[c][d];
            sc[c] = a;
        }
        float mnew = m;
        #pragma unroll
        for (int c = 0; c < 32; c++) {
            int col  = c0 + c;
            int diff = row - col; diff = (diff < 0) ? -diff : diff;
            if (diff >= WIN) sc[c] = -INFINITY;
            else if (sc[c] > mnew) mnew = sc[c];
        }
        if (mnew != -INFINITY) {
            float corr = expf(m - mnew);      // m=-inf -> 0
            l *= corr;
            #pragma unroll
            for (int d = 0; d < 64; d++) o[d] *= corr;
            #pragma unroll
            for (int c = 0; c < 32; c++) {
                float p = (sc[c] == -INFINITY) ? 0.f : expf(sc[c] - mnew);
                l += p;
                #pragma unroll
                for (int d = 0; d < 64; d++) o[d] += p * vs[c][d];
            }
            m = mnew;
        }
    }

    float invl = 1.f / l;
    float* op = out + (size_t)row * DM + h * HD;
    #pragma unroll
    for (int i = 0; i < 16; i++) {
        float4 v = make_float4(o[4*i+0]*invl, o[4*i+1]*invl, o[4*i+2]*invl, o[4*i+3]*invl);
        *(float4*)(op + 4 * i) = v;
    }
}

// ---------------- fused residual + LayerNorm (in-place on x) -------------
__global__ __launch_bounds__(256) void ln_residual_kernel(
    float* __restrict__ x, const float* __restrict__ y,
    const float* __restrict__ g, const float* __restrict__ b)
{
    int s = blockIdx.x, t = threadIdx.x;
    float* xr = x + (size_t)s * DM;
    const float* yr = y + (size_t)s * DM;

    float v[4], sum = 0.f, sq = 0.f;
    #pragma unroll
    for (int i = 0; i < 4; i++) {
        int d = i * 256 + t;
        v[i] = xr[d] + yr[d];
        sum += v[i];
        sq  += v[i] * v[i];
    }
    #pragma unroll
    for (int off = 16; off; off >>= 1) {
        sum += __shfl_xor_sync(0xffffffffu, sum, off);
        sq  += __shfl_xor_sync(0xffffffffu, sq,  off);
    }
    __shared__ float s_sum[8], s_sq[8];
    int w = t >> 5;
    if ((t & 31) == 0) { s_sum[w] = sum; s_sq[w] = sq; }
    __syncthreads();
    float ts = 0.f, tq = 0.f;
    #pragma unroll
    for (int i = 0; i < 8; i++) { ts += s_sum[i]; tq += s_sq[i]; }

    float mean = ts * (1.f / DM);
    float var  = tq * (1.f / DM) - mean * mean;
    var = fmaxf(var, 0.f);
    float inv = rsqrtf(var + 1e-5f);
    #pragma unroll
    for (int i = 0; i < 4; i++) {
        int d = i * 256 + t;
        xr[d] = (v[i] - mean) * inv * g[d] + b[d];
    }
}

// ---------------- decoder: logits (D->3) + log_softmax -------------------
__global__ __launch_bounds__(128) void decode_kernel(
    const float* __restrict__ x, const float* __restrict__ W,
    const float* __restrict__ bd, float* __restrict__ out)
{
    int s = blockIdx.x, t = threadIdx.x;
    const float* xr = x + (size_t)s * DM;
    float p0 = 0.f, p1 = 0.f, p2 = 0.f;
    for (int d = t; d < DM; d += 128) {
        float xv = xr[d];
        p0 += xv * W[d];
        p1 += xv * W[DM + d];
        p2 += xv * W[2 * DM + d];
    }
    #pragma unroll
    for (int off = 16; off; off >>= 1) {
        p0 += __shfl_xor_sync(0xffffffffu, p0, off);
        p1 += __shfl_xor_sync(0xffffffffu, p1, off);
        p2 += __shfl_xor_sync(0xffffffffu, p2, off);
    }
    __shared__ float r0[4], r1[4], r2[4];
    int w = t >> 5;
    if ((t & 31) == 0) { r0[w] = p0; r1[w] = p1; r2[w] = p2; }
    __syncthreads();
    if (t == 0) {
        float l0 = r0[0]+r0[1]+r0[2]+r0[3] + bd[0];
        float l1 = r1[0]+r1[1]+r1[2]+r1[3] + bd[1];
        float l2 = r2[0]+r2[1]+r2[2]+r2[3] + bd[2];
        float mx  = fmaxf(l0, fmaxf(l1, l2));
        float lse = mx + logf(expf(l0-mx) + expf(l1-mx) + expf(l2-mx));
        out[s*3+0] = l0 - lse;
        out[s*3+1] = l1 - lse;
        out[s*3+2] = l2 - lse;
    }
}

// ---------------- launch ---------------------------------------------------
extern "C" void kernel_launch(void* const* d_in, const int* in_sizes, int n_in,
                              void* d_out, int out_size)
{
    const float* X     = (const float*)d_in[0];
    const float* Wqkv  = (const float*)d_in[1];
    const float* bqkv  = (const float*)d_in[2];
    const float* Wo    = (const float*)d_in[3];
    const float* bo    = (const float*)d_in[4];
    const float* ln1g  = (const float*)d_in[5];
    const float* ln1b  = (const float*)d_in[6];
    const float* W1    = (const float*)d_in[7];
    const float* b1    = (const float*)d_in[8];
    const float* W2    = (const float*)d_in[9];
    const float* b2    = (const float*)d_in[10];
    const float* ln2g  = (const float*)d_in[11];
    const float* ln2b  = (const float*)d_in[12];
    const float* Wdec  = (const float*)d_in[13];
    const float* bdec  = (const float*)d_in[14];

    float *x, *qkv, *att, *hbuf, *ybuf;
    cudaGetSymbolAddress((void**)&x,    g_x);
    cudaGetSymbolAddress((void**)&qkv,  g_qkv);
    cudaGetSymbolAddress((void**)&att,  g_att);
    cudaGetSymbolAddress((void**)&hbuf, g_h);
    cudaGetSymbolAddress((void**)&ybuf, g_y);

    add_pe_kernel<<<(SEQ * DM) / 256, 256>>>(X, x);

    for (int l = 0; l < NL; l++) {
        // QKV projection: [2048,1024] x [3072,1024]^T
        gemm_nt<0><<<dim3(3 * DM / 128, SEQ / 128), 256>>>(
            x, Wqkv + (size_t)l * 3 * DM * DM, bqkv + (size_t)l * 3 * DM,
            qkv, SEQ, 3 * DM, DM);

        // banded attention
        attention_kernel<<<dim3(SEQ / 128, NH), 128>>>(qkv, att);

        // output projection
        gemm_nt<0><<<dim3(DM / 128, SEQ / 128), 256>>>(
            att, Wo + (size_t)l * DM * DM, bo + (size_t)l * DM,
            ybuf, SEQ, DM, DM);

        // x = LN1(x + attn_proj)
        ln_residual_kernel<<<SEQ, 256>>>(x, ybuf, ln1g + (size_t)l * DM, ln1b + (size_t)l * DM);

        // FF1 + ReLU: [2048,1024] x [4096,1024]^T
        gemm_nt<1><<<dim3(DFF / 128, SEQ / 128), 256>>>(
            x, W1 + (size_t)l * DFF * DM, b1 + (size_t)l * DFF,
            hbuf, SEQ, DFF, DM);

        // FF2: [2048,4096] x [1024,4096]^T
        gemm_nt<0><<<dim3(DM / 128, SEQ / 128), 256>>>(
            hbuf, W2 + (size_t)l * DM * DFF, b2 + (size_t)l * DM,
            ybuf, SEQ, DM, DFF);

        // x = LN2(x + ff)
        ln_residual_kernel<<<SEQ, 256>>>(x, ybuf, ln2g + (size_t)l * DM, ln2b + (size_t)l * DM);
    }

    decode_kernel<<<SEQ, 128>>>(x, Wdec, bdec, (float*)d_out);
}

// round 14
// speedup vs baseline: 1.0002x; 1.0001x over previous
#include <cuda_runtime.h>
#include <math.h>

#define SEQ   2048
#define DM    1024
#define NH    16
#define HD    64
#define DFF   4096
#define NL    4
#define WIN   128

// ---------------- scratch (device globals; no runtime allocation) ----------
__device__ float g_x  [SEQ * DM];        // residual stream
__device__ float g_qkv[SEQ * 3 * DM];    // fused qkv
__device__ float g_att[SEQ * DM];        // attention output
__device__ float g_h  [SEQ * DFF];       // FF hidden
__device__ float g_y  [SEQ * DM];        // proj / FF2 output

// ---------------- positional encoding add (fp64 trig: fast-math immune) ----
__global__ void add_pe_kernel(const float* __restrict__ X, float* __restrict__ x)
{
    int i = blockIdx.x * 256 + threadIdx.x;       // over SEQ*DM
    int s = i >> 10;
    int d = i & 1023;
    double dv  = exp((double)(d & ~1) * (-9.210340371976184 / 1024.0));
    double ang = (double)s * dv;
    float pe = (d & 1) ? (float)cos(ang) : (float)sin(ang);
    x[i] = X[i] + pe;
}

// ---------------- GEMM NT: C[M,N] = A[M,K] * B[N,K]^T + bias, opt ReLU -----
// 128x128 tile, BK=16, 256 threads, 8x8 per-thread register tile.
template<int RELU>
__global__ __launch_bounds__(256) void gemm_nt(
    const float* __restrict__ A, const float* __restrict__ B,
    const float* __restrict__ bias, float* __restrict__ C,
    int M, int N, int K)
{
    __shared__ float As[16][132];
    __shared__ float Bs[16][132];

    const int tid = threadIdx.x;
    const int m0  = blockIdx.y * 128;
    const int n0  = blockIdx.x * 128;
    const int tr  = tid >> 4;       // 0..15
    const int tc  = tid & 15;       // 0..15

    float acc[8][8];
    #pragma unroll
    for (int i = 0; i < 8; i++)
        #pragma unroll
        for (int j = 0; j < 8; j++) acc[i][j] = 0.f;

    for (int k0 = 0; k0 < K; k0 += 16) {
        #pragma unroll
        for (int i = 0; i < 2; i++) {
            int idx = tid + 256 * i;          // 0..511
            int r   = idx >> 2;               // 0..127
            int kc  = (idx & 3) << 2;         // 0,4,8,12
            float4 va = *(const float4*)(A + (size_t)(m0 + r) * K + k0 + kc);
            As[kc + 0][r] = va.x; As[kc + 1][r] = va.y;
            As[kc + 2][r] = va.z; As[kc + 3][r] = va.w;
            float4 vb = *(const float4*)(B + (size_t)(n0 + r) * K + k0 + kc);
            Bs[kc + 0][r] = vb.x; Bs[kc + 1][r] = vb.y;
            Bs[kc + 2][r] = vb.z; Bs[kc + 3][r] = vb.w;
        }
        __syncthreads();
        #pragma unroll
        for (int kk = 0; kk < 16; kk++) {
            float a[8], b[8];
            *(float4*)(a)     = *(const float4*)&As[kk][tr * 8];
            *(float4*)(a + 4) = *(const float4*)&As[kk][tr * 8 + 4];
            *(float4*)(b)     = *(const float4*)&Bs[kk][tc * 8];
            *(float4*)(b + 4) = *(const float4*)&Bs[kk][tc * 8 + 4];
            #pragma unroll
            for (int i = 0; i < 8; i++)
                #pragma unroll
                for (int j = 0; j < 8; j++)
                    acc[i][j] += a[i] * b[j];
        }
        __syncthreads();
    }

    #pragma unroll
    for (int i = 0; i < 8; i++) {
        int row = m0 + tr * 8 + i;
        #pragma unroll
        for (int j = 0; j < 8; j += 4) {
            int col = n0 + tc * 8 + j;
            float4 v;
            v.x = acc[i][j + 0] + bias[col + 0];
            v.y = acc[i][j + 1] + bias[col + 1];
            v.z = acc[i][j + 2] + bias[col + 2];
            v.w = acc[i][j + 3] + bias[col + 3];
            if (RELU) {
                v.x = fmaxf(v.x, 0.f); v.y = fmaxf(v.y, 0.f);
                v.z = fmaxf(v.z, 0.f); v.w = fmaxf(v.w, 0.f);
            }
            *(float4*)(C + (size_t)row * N + col) = v;
        }
    }
}

// ---------------- banded flash attention --------------------------------
// grid: (SEQ/128, NH), 128 threads. Each thread owns one query row (q, o in
// registers), streams 32-row K/V tiles through shared memory, online softmax.
__global__ __launch_bounds__(128) void attention_kernel(
    const float* __restrict__ qkv, float* __restrict__ out)
{
    const int h   = blockIdx.y;
    const int r0  = blockIdx.x * 128;
    const int tid = threadIdx.x;
    const int row = r0 + tid;

    __shared__ float ks[32][64];
    __shared__ float vs[32][64];

    float q[64];
    {
        const float4* qp = (const float4*)(qkv + (size_t)row * (3 * DM) + h * HD);
        #pragma unroll
        for (int i = 0; i < 16; i++) {
            float4 v = qp[i];
            q[4*i+0] = v.x * 0.125f; q[4*i+1] = v.y * 0.125f;
            q[4*i+2] = v.z * 0.125f; q[4*i+3] = v.w * 0.125f;
        }
    }
    float o[64];
    #pragma unroll
    for (int d = 0; d < 64; d++) o[d] = 0.f;
    float m = -INFINITY, l = 0.f;

    int cmin = r0 - (WIN - 1); if (cmin < 0) cmin = 0;
    int cmax = r0 + 127 + (WIN - 1); if (cmax > SEQ - 1) cmax = SEQ - 1;

    for (int c0 = cmin & ~31; c0 <= cmax; c0 += 32) {
        __syncthreads();
        #pragma unroll
        for (int i = 0; i < 4; i++) {
            int idx = tid + 128 * i;          // 0..511
            int r   = idx >> 4;               // 0..31
            int d4  = (idx & 15) << 2;        // 0..60
            *(float4*)&ks[r][d4] =
                *(const float4*)(qkv + (size_t)(c0 + r) * (3 * DM) + DM + h * HD + d4);
            *(float4*)&vs[r][d4] =
                *(const float4*)(qkv + (size_t)(c0 + r) * (3 * DM) + 2 * DM + h * HD + d4);
        }
        __syncthreads();

        float sc[32];
        #pragma unroll
        for (int c = 0; c < 32; c++) {
            float a = 0.f;
            #pragma unroll
            for (int d = 0; d < 64; d++) a += q[d] * ks[c][d];
            sc[c] = a;
        }
        float mnew = m;
        #pragma unroll
        for (int c = 0; c < 32; c++) {
            int col  = c0 + c;
            int diff = row - col; diff = (diff < 0) ? -diff : diff;
            if (diff >= WIN) sc[c] = -INFINITY;
            else if (sc[c] > mnew) mnew = sc[c];
        }
        if (mnew != -INFINITY) {
            float corr = expf(m - mnew);      // m=-inf -> 0
            l *= corr;
            #pragma unroll
            for (int d = 0; d < 64; d++) o[d] *= corr;
            #pragma unroll
            for (int c = 0; c < 32; c++) {
                float p = (sc[c] == -INFINITY) ? 0.f : expf(sc[c] - mnew);
                l += p;
                #pragma unroll
                for (int d = 0; d < 64; d++) o[d] += p * vs[c][d];
            }
            m = mnew;
        }
    }

    float invl = 1.f / l;
    float* op = out + (size_t)row * DM + h * HD;
    #pragma unroll
    for (int i = 0; i < 16; i++) {
        float4 v = make_float4(o[4*i+0]*invl, o[4*i+1]*invl, o[4*i+2]*invl, o[4*i+3]*invl);
        *(float4*)(op + 4 * i) = v;
    }
}

// ---------------- fused residual + LayerNorm (in-place on x) -------------
__global__ __launch_bounds__(256) void ln_residual_kernel(
    float* __restrict__ x, const float* __restrict__ y,
    const float* __restrict__ g, const float* __restrict__ b)
{
    int s = blockIdx.x, t = threadIdx.x;
    float* xr = x + (size_t)s * DM;
    const float* yr = y + (size_t)s * DM;

    float v[4], sum = 0.f, sq = 0.f;
    #pragma unroll
    for (int i = 0; i < 4; i++) {
        int d = i * 256 + t;
        v[i] = xr[d] + yr[d];
        sum += v[i];
        sq  += v[i] * v[i];
    }
    #pragma unroll
    for (int off = 16; off; off >>= 1) {
        sum += __shfl_xor_sync(0xffffffffu, sum, off);
        sq  += __shfl_xor_sync(0xffffffffu, sq,  off);
    }
    __shared__ float s_sum[8], s_sq[8];
    int w = t >> 5;
    if ((t & 31) == 0) { s_sum[w] = sum; s_sq[w] = sq; }
    __syncthreads();
    float ts = 0.f, tq = 0.f;
    #pragma unroll
    for (int i = 0; i < 8; i++) { ts += s_sum[i]; tq += s_sq[i]; }

    float mean = ts * (1.f / DM);
    float var  = tq * (1.f / DM) - mean * mean;
    var = fmaxf(var, 0.f);
    float inv = rsqrtf(var + 1e-5f);
    #pragma unroll
    for (int i = 0; i < 4; i++) {
        int d = i * 256 + t;
        xr[d] = (v[i] - mean) * inv * g[d] + b[d];
    }
}

// ---------------- decoder: logits (D->3) + log_softmax -------------------
__global__ __launch_bounds__(128) void decode_kernel(
    const float* __restrict__ x, const float* __restrict__ W,
    const float* __restrict__ bd, float* __restrict__ out)
{
    int s = blockIdx.x, t = threadIdx.x;
    const float* xr = x + (size_t)s * DM;
    float p0 = 0.f, p1 = 0.f, p2 = 0.f;
    for (int d = t; d < DM; d += 128) {
        float xv = xr[d];
        p0 += xv * W[d];
        p1 += xv * W[DM + d];
        p2 += xv * W[2 * DM + d];
    }
    #pragma unroll
    for (int off = 16; off; off >>= 1) {
        p0 += __shfl_xor_sync(0xffffffffu, p0, off);
        p1 += __shfl_xor_sync(0xffffffffu, p1, off);
        p2 += __shfl_xor_sync(0xffffffffu, p2, off);
    }
    __shared__ float r0[4], r1[4], r2[4];
    int w = t >> 5;
    if ((t & 31) == 0) { r0[w] = p0; r1[w] = p1; r2[w] = p2; }
    __syncthreads();
    if (t == 0) {
        float l0 = r0[0]+r0[1]+r0[2]+r0[3] + bd[0];
        float l1 = r1[0]+r1[1]+r1[2]+r1[3] + bd[1];
        float l2 = r2[0]+r2[1]+r2[2]+r2[3] + bd[2];
        float mx  = fmaxf(l0, fmaxf(l1, l2));
        float lse = mx + logf(expf(l0-mx) + expf(l1-mx) + expf(l2-mx));
        out[s*3+0] = l0 - lse;
        out[s*3+1] = l1 - lse;
        out[s*3+2] = l2 - lse;
    }
}

// ---------------- launch ---------------------------------------------------
extern "C" void kernel_launch(void* const* d_in, const int* in_sizes, int n_in,
                              void* d_out, int out_size)
{
    const float* X     = (const float*)d_in[0];
    const float* Wqkv  = (const float*)d_in[1];
    const float* bqkv  = (const float*)d_in[2];
    const float* Wo    = (const float*)d_in[3];
    const float* bo    = (const float*)d_in[4];
    const float* ln1g  = (const float*)d_in[5];
    const float* ln1b  = (const float*)d_in[6];
    const float* W1    = (const float*)d_in[7];
    const float* b1    = (const float*)d_in[8];
    const float* W2    = (const float*)d_in[9];
    const float* b2    = (const float*)d_in[10];
    const float* ln2g  = (const float*)d_in[11];
    const float* ln2b  = (const float*)d_in[12];
    const float* Wdec  = (const float*)d_in[13];
    const float* bdec  = (const float*)d_in[14];

    float *x, *qkv, *att, *hbuf, *ybuf;
    cudaGetSymbolAddress((void**)&x,    g_x);
    cudaGetSymbolAddress((void**)&qkv,  g_qkv);
    cudaGetSymbolAddress((void**)&att,  g_att);
    cudaGetSymbolAddress((void**)&hbuf, g_h);
    cudaGetSymbolAddress((void**)&ybuf, g_y);

    add_pe_kernel<<<(SEQ * DM) / 256, 256>>>(X, x);

    for (int l = 0; l < NL; l++) {
        // QKV projection: [2048,1024] x [3072,1024]^T
        gemm_nt<0><<<dim3(3 * DM / 128, SEQ / 128), 256>>>(
            x, Wqkv + (size_t)l * 3 * DM * DM, bqkv + (size_t)l * 3 * DM,
            qkv, SEQ, 3 * DM, DM);

        // banded attention
        attention_kernel<<<dim3(SEQ / 128, NH), 128>>>(qkv, att);

        // output projection
        gemm_nt<0><<<dim3(DM / 128, SEQ / 128), 256>>>(
            att, Wo + (size_t)l * DM * DM, bo + (size_t)l * DM,
            ybuf, SEQ, DM, DM);

        // x = LN1(x + attn_proj)
        ln_residual_kernel<<<SEQ, 256>>>(x, ybuf, ln1g + (size_t)l * DM, ln1b + (size_t)l * DM);

        // FF1 + ReLU: [2048,1024] x [4096,1024]^T
        gemm_nt<1><<<dim3(DFF / 128, SEQ / 128), 256>>>(
            x, W1 + (size_t)l * DFF * DM, b1 + (size_t)l * DFF,
            hbuf, SEQ, DFF, DM);

        // FF2: [2048,4096] x [1024,4096]^T
        gemm_nt<0><<<dim3(DM / 128, SEQ / 128), 256>>>(
            hbuf, W2 + (size_t)l * DM * DFF, b2 + (size_t)l * DM,
            ybuf, SEQ, DM, DFF);

        // x = LN2(x + ff)
        ln_residual_kernel<<<SEQ, 256>>>(x, ybuf, ln2g + (size_t)l * DM, ln2b + (size_t)l * DM);
    }

    decode_kernel<<<SEQ, 128>>>(x, Wdec, bdec, (float*)d_out);
}

// round 15
// speedup vs baseline: 1.0125x; 1.0123x over previous
#include <cuda_runtime.h>
#include <math.h>

#define SEQ   2048
#define DM    1024
#define NH    16
#define HD    64
#define DFF   4096
#define NL    4
#define WIN   128

// ---------------- scratch (device globals; no runtime allocation) ----------
__device__ float g_x  [SEQ * DM];        // residual stream
__device__ float g_qkv[SEQ * 3 * DM];    // fused qkv
__device__ float g_att[SEQ * DM];        // attention output
__device__ float g_h  [SEQ * DFF];       // FF hidden
__device__ float g_y  [SEQ * DM];        // proj / FF2 output

// ---------------- positional encoding add (fp64 trig: fast-math immune) ----
__global__ void add_pe_kernel(const float* __restrict__ X, float* __restrict__ x)
{
    int i = blockIdx.x * 256 + threadIdx.x;       // over SEQ*DM
    int s = i >> 10;
    int d = i & 1023;
    double dv  = exp((double)(d & ~1) * (-9.210340371976184 / 1024.0));
    double ang = (double)s * dv;
    float pe = (d & 1) ? (float)cos(ang) : (float)sin(ang);
    x[i] = X[i] + pe;
}

// ---------------- GEMM NT: C[M,N] = A[M,K] * B[N,K]^T + bias, opt ReLU -----
// 128x128 tile, BK=16, 256 threads, 8x8 per-thread register tile.
template<int RELU>
__global__ __launch_bounds__(256) void gemm_nt(
    const float* __restrict__ A, const float* __restrict__ B,
    const float* __restrict__ bias, float* __restrict__ C,
    int M, int N, int K)
{
    __shared__ float As[16][132];
    __shared__ float Bs[16][132];

    const int tid = threadIdx.x;
    const int m0  = blockIdx.y * 128;
    const int n0  = blockIdx.x * 128;
    const int tr  = tid >> 4;       // 0..15
    const int tc  = tid & 15;       // 0..15

    float acc[8][8];
    #pragma unroll
    for (int i = 0; i < 8; i++)
        #pragma unroll
        for (int j = 0; j < 8; j++) acc[i][j] = 0.f;

    for (int k0 = 0; k0 < K; k0 += 16) {
        #pragma unroll
        for (int i = 0; i < 2; i++) {
            int idx = tid + 256 * i;          // 0..511
            int r   = idx >> 2;               // 0..127
            int kc  = (idx & 3) << 2;         // 0,4,8,12
            float4 va = *(const float4*)(A + (size_t)(m0 + r) * K + k0 + kc);
            As[kc + 0][r] = va.x; As[kc + 1][r] = va.y;
            As[kc + 2][r] = va.z; As[kc + 3][r] = va.w;
            float4 vb = *(const float4*)(B + (size_t)(n0 + r) * K + k0 + kc);
            Bs[kc + 0][r] = vb.x; Bs[kc + 1][r] = vb.y;
            Bs[kc + 2][r] = vb.z; Bs[kc + 3][r] = vb.w;
        }
        __syncthreads();
        #pragma unroll
        for (int kk = 0; kk < 16; kk++) {
            float a[8], b[8];
            *(float4*)(a)     = *(const float4*)&As[kk][tr * 8];
            *(float4*)(a + 4) = *(const float4*)&As[kk][tr * 8 + 4];
            *(float4*)(b)     = *(const float4*)&Bs[kk][tc * 8];
            *(float4*)(b + 4) = *(const float4*)&Bs[kk][tc * 8 + 4];
            #pragma unroll
            for (int i = 0; i < 8; i++)
                #pragma unroll
                for (int j = 0; j < 8; j++)
                    acc[i][j] += a[i] * b[j];
        }
        __syncthreads();
    }

    #pragma unroll
    for (int i = 0; i < 8; i++) {
        int row = m0 + tr * 8 + i;
        #pragma unroll
        for (int j = 0; j < 8; j += 4) {
            int col = n0 + tc * 8 + j;
            float4 v;
            v.x = acc[i][j + 0] + bias[col + 0];
            v.y = acc[i][j + 1] + bias[col + 1];
            v.z = acc[i][j + 2] + bias[col + 2];
            v.w = acc[i][j + 3] + bias[col + 3];
            if (RELU) {
                v.x = fmaxf(v.x, 0.f); v.y = fmaxf(v.y, 0.f);
                v.z = fmaxf(v.z, 0.f); v.w = fmaxf(v.w, 0.f);
            }
            *(float4*)(C + (size_t)row * N + col) = v;
        }
    }
}

// ---------------- banded flash attention --------------------------------
// grid: (SEQ/128, NH), 128 threads. Each thread owns one query row (q, o in
// registers), streams 32-row K/V tiles through shared memory, online softmax.
__global__ __launch_bounds__(128) void attention_kernel(
    const float* __restrict__ qkv, float* __restrict__ out)
{
    const int h   = blockIdx.y;
    const int r0  = blockIdx.x * 128;
    const int tid = threadIdx.x;
    const int row = r0 + tid;

    __shared__ float ks[32][64];
    __shared__ float vs[32][64];

    float q[64];
    {
        const float4* qp = (const float4*)(qkv + (size_t)row * (3 * DM) + h * HD);
        #pragma unroll
        for (int i = 0; i < 16; i++) {
            float4 v = qp[i];
            q[4*i+0] = v.x * 0.125f; q[4*i+1] = v.y * 0.125f;
            q[4*i+2] = v.z * 0.125f; q[4*i+3] = v.w * 0.125f;
        }
    }
    float o[64];
    #pragma unroll
    for (int d = 0; d < 64; d++) o[d] = 0.f;
    float m = -INFINITY, l = 0.f;

    int cmin = r0 - (WIN - 1); if (cmin < 0) cmin = 0;
    int cmax = r0 + 127 + (WIN - 1); if (cmax > SEQ - 1) cmax = SEQ - 1;

    for (int c0 = cmin & ~31; c0 <= cmax; c0 += 32) {
        __syncthreads();
        #pragma unroll
        for (int i = 0; i < 4; i++) {
            int idx = tid + 128 * i;          // 0..511
            int r   = idx >> 4;               // 0..31
            int d4  = (idx & 15) << 2;        // 0..60
            *(float4*)&ks[r][d4] =
                *(const float4*)(qkv + (size_t)(c0 + r) * (3 * DM) + DM + h * HD + d4);
            *(float4*)&vs[r][d4] =
                *(const float4*)(qkv + (size_t)(c0 + r) * (3 * DM) + 2 * DM + h * HD + d4);
        }
        __syncthreads();

        float sc[32];
        #pragma unroll
        for (int c = 0; c < 32; c++) {
            float a = 0.f;
            #pragma unroll
            for (int d = 0; d < 64; d++) a += q[d] * ks[c][d];
            sc[c] = a;
        }
        float mnew = m;
        #pragma unroll
        for (int c = 0; c < 32; c++) {
            int col  = c0 + c;
            int diff = row - col; diff = (diff < 0) ? -diff : diff;
            if (diff >= WIN) sc[c] = -INFINITY;
            else if (sc[c] > mnew) mnew = sc[c];
        }
        if (mnew != -INFINITY) {
            float corr = expf(m - mnew);      // m=-inf -> 0
            l *= corr;
            #pragma unroll
            for (int d = 0; d < 64; d++) o[d] *= corr;
            #pragma unroll
            for (int c = 0; c < 32; c++) {
                float p = (sc[c] == -INFINITY) ? 0.f : expf(sc[c] - mnew);
                l += p;
                #pragma unroll
                for (int d = 0; d < 64; d++) o[d] += p * vs[c][d];
            }
            m = mnew;
        }
    }

    float invl = 1.f / l;
    float* op = out + (size_t)row * DM + h * HD;
    #pragma unroll
    for (int i = 0; i < 16; i++) {
        float4 v = make_float4(o[4*i+0]*invl, o[4*i+1]*invl, o[4*i+2]*invl, o[4*i+3]*invl);
        *(float4*)(op + 4 * i) = v;
    }
}

// ---------------- fused residual + LayerNorm (in-place on x) -------------
__global__ __launch_bounds__(256) void ln_residual_kernel(
    float* __restrict__ x, const float* __restrict__ y,
    const float* __restrict__ g, const float* __restrict__ b)
{
    int s = blockIdx.x, t = threadIdx.x;
    float* xr = x + (size_t)s * DM;
    const float* yr = y + (size_t)s * DM;

    float v[4], sum = 0.f, sq = 0.f;
    #pragma unroll
    for (int i = 0; i < 4; i++) {
        int d = i * 256 + t;
        v[i] = xr[d] + yr[d];
        sum += v[i];
        sq  += v[i] * v[i];
    }
    #pragma unroll
    for (int off = 16; off; off >>= 1) {
        sum += __shfl_xor_sync(0xffffffffu, sum, off);
        sq  += __shfl_xor_sync(0xffffffffu, sq,  off);
    }
    __shared__ float s_sum[8], s_sq[8];
    int w = t >> 5;
    if ((t & 31) == 0) { s_sum[w] = sum; s_sq[w] = sq; }
    __syncthreads();
    float ts = 0.f, tq = 0.f;
    #pragma unroll
    for (int i = 0; i < 8; i++) { ts += s_sum[i]; tq += s_sq[i]; }

    float mean = ts * (1.f / DM);
    float var  = tq * (1.f / DM) - mean * mean;
    var = fmaxf(var, 0.f);
    float inv = rsqrtf(var + 1e-5f);
    #pragma unroll
    for (int i = 0; i < 4; i++) {
        int d = i * 256 + t;
        xr[d] = (v[i] - mean) * inv * g[d] + b[d];
    }
}

// ---------------- decoder: logits (D->3) + log_softmax -------------------
__global__ __launch_bounds__(128) void decode_kernel(
    const float* __restrict__ x, const float* __restrict__ W,
    const float* __restrict__ bd, float* __restrict__ out)
{
    int s = blockIdx.x, t = threadIdx.x;
    const float* xr = x + (size_t)s * DM;
    float p0 = 0.f, p1 = 0.f, p2 = 0.f;
    for (int d = t; d < DM; d += 128) {
        float xv = xr[d];
        p0 += xv * W[d];
        p1 += xv * W[DM + d];
        p2 += xv * W[2 * DM + d];
    }
    #pragma unroll
    for (int off = 16; off; off >>= 1) {
        p0 += __shfl_xor_sync(0xffffffffu, p0, off);
        p1 += __shfl_xor_sync(0xffffffffu, p1, off);
        p2 += __shfl_xor_sync(0xffffffffu, p2, off);
    }
    __shared__ float r0[4], r1[4], r2[4];
    int w = t >> 5;
    if ((t & 31) == 0) { r0[w] = p0; r1[w] = p1; r2[w] = p2; }
    __syncthreads();
    if (t == 0) {
        float l0 = r0[0]+r0[1]+r0[2]+r0[3] + bd[0];
        float l1 = r1[0]+r1[1]+r1[2]+r1[3] + bd[1];
        float l2 = r2[0]+r2[1]+r2[2]+r2[3] + bd[2];
        float mx  = fmaxf(l0, fmaxf(l1, l2));
        float lse = mx + logf(expf(l0-mx) + expf(l1-mx) + expf(l2-mx));
        out[s*3+0] = l0 - lse;
        out[s*3+1] = l1 - lse;
        out[s*3+2] = l2 - lse;
    }
}

// ---------------- launch ---------------------------------------------------
extern "C" void kernel_launch(void* const* d_in, const int* in_sizes, int n_in,
                              void* d_out, int out_size)
{
    const float* X     = (const float*)d_in[0];
    const float* Wqkv  = (const float*)d_in[1];
    const float* bqkv  = (const float*)d_in[2];
    const float* Wo    = (const float*)d_in[3];
    const float* bo    = (const float*)d_in[4];
    const float* ln1g  = (const float*)d_in[5];
    const float* ln1b  = (const float*)d_in[6];
    const float* W1    = (const float*)d_in[7];
    const float* b1    = (const float*)d_in[8];
    const float* W2    = (const float*)d_in[9];
    const float* b2    = (const float*)d_in[10];
    const float* ln2g  = (const float*)d_in[11];
    const float* ln2b  = (const float*)d_in[12];
    const float* Wdec  = (const float*)d_in[13];
    const float* bdec  = (const float*)d_in[14];

    float *x, *qkv, *att, *hbuf, *ybuf;
    cudaGetSymbolAddress((void**)&x,    g_x);
    cudaGetSymbolAddress((void**)&qkv,  g_qkv);
    cudaGetSymbolAddress((void**)&att,  g_att);
    cudaGetSymbolAddress((void**)&hbuf, g_h);
    cudaGetSymbolAddress((void**)&ybuf, g_y);

    add_pe_kernel<<<(SEQ * DM) / 256, 256>>>(X, x);

    for (int l = 0; l < NL; l++) {
        // QKV projection: [2048,1024] x [3072,1024]^T
        gemm_nt<0><<<dim3(3 * DM / 128, SEQ / 128), 256>>>(
            x, Wqkv + (size_t)l * 3 * DM * DM, bqkv + (size_t)l * 3 * DM,
            qkv, SEQ, 3 * DM, DM);

        // banded attention
        attention_kernel<<<dim3(SEQ / 128, NH), 128>>>(qkv, att);

        // output projection
        gemm_nt<0><<<dim3(DM / 128, SEQ / 128), 256>>>(
            att, Wo + (size_t)l * DM * DM, bo + (size_t)l * DM,
            ybuf, SEQ, DM, DM);

        // x = LN1(x + attn_proj)
        ln_residual_kernel<<<SEQ, 256>>>(x, ybuf, ln1g + (size_t)l * DM, ln1b + (size_t)l * DM);

        // FF1 + ReLU: [2048,1024] x [4096,1024]^T
        gemm_nt<1><<<dim3(DFF / 128, SEQ / 128), 256>>>(
            x, W1 + (size_t)l * DFF * DM, b1 + (size_t)l * DFF,
            hbuf, SEQ, DFF, DM);

        // FF2: [2048,4096] x [1024,4096]^T
        gemm_nt<0><<<dim3(DM / 128, SEQ / 128), 256>>>(
            hbuf, W2 + (size_t)l * DM * DFF, b2 + (size_t)l * DM,
            ybuf, SEQ, DM, DFF);

        // x = LN2(x + ff)
        ln_residual_kernel<<<SEQ, 256>>>(x, ybuf, ln2g + (size_t)l * DM, ln2b + (size_t)l * DM);
    }

    decode_kernel<<<SEQ, 128>>>(x, Wdec, bdec, (float*)d_out);
}